// round 3
// baseline (speedup 1.0000x reference)
#include <cuda_runtime.h>
#include <cstdint>

// HyenaSE gated causal depthwise conv, bdl layout.
// y[b,d,l] = q * sum_{s=0}^{127} (k*x)[b,d,l-s] * h[d%256][127-s]
//
// One block per (batch, channel-pair (d, d+2048)) -- the pair shares a filter
// group (2048 % 256 == 0). kx streams interleaved into a float2 shared buffer,
// mainloop uses packed fma.rn.f32x2 (2 FMAs/instr; 3-reg FFMA is half-rate on
// sm_103a). Register-tiled FIR: 16 outputs/thread x 8-tap chunks -> 23 LDS.64
// feed 128 FFMA2 per chunk. Shared buffer padded every 16 float2 to kill the
// 32-way bank conflict from the 128B thread stride. Global paths use
// float4 LDG / STG.128.

typedef unsigned long long u64;

#define B_  2
#define D_  4096
#define L_  4096
#define G_  256
#define HL_ 128

static constexpr int THREADS = 256;
static constexpr int TPT = 16;             // outputs per thread (L / THREADS)
static constexpr int U   = 8;              // taps per chunk
static constexpr int N2  = HL_ - 1 + L_;   // 4223 float2 (127 pad + 4096)
__device__ __forceinline__ int padidx(int r) { return r + (r >> 4); }
static constexpr int NPAD = N2 + ((N2 - 1) >> 4) + 1;  // 4486

__device__ __forceinline__ void ffma2(u64& acc, u64 a, u64 b) {
    asm("fma.rn.f32x2 %0, %1, %2, %0;" : "+l"(acc) : "l"(a), "l"(b));
}

__global__ void __launch_bounds__(THREADS, 2)
hyena_se_kernel(const float* __restrict__ x, const float* __restrict__ k,
                const float* __restrict__ q, const float* __restrict__ h,
                float* __restrict__ out)
{
    __shared__ u64 sh[NPAD];   // interleaved kx pairs, padded
    __shared__ u64 w2[HL_];    // reversed filter, duplicated into both lanes

    const int tid = threadIdx.x;
    const int b   = blockIdx.x >> 11;
    const int dp  = blockIdx.x & 2047;
    const long row0 = (long)(b * D_ + dp) * L_;
    const long row1 = (long)(b * D_ + dp + 2048) * L_;
    const int g = dp & (G_ - 1);

    // Reversed filter: wrev[s] = h[g][HL-1-s], packed {w,w}
    for (int s = tid; s < HL_; s += THREADS) {
        unsigned wb = __float_as_uint(h[g * HL_ + (HL_ - 1 - s)]);
        w2[s] = ((u64)wb << 32) | (u64)wb;
    }
    // Causal left pad (zeros)
    for (int r = tid; r < HL_ - 1; r += THREADS) sh[padidx(r)] = 0ULL;

    // kx fill, float4 LDG (each thread: 4 iterations of 4 consecutive floats)
    {
        const float4* x0 = (const float4*)(x + row0);
        const float4* k0 = (const float4*)(k + row0);
        const float4* x1 = (const float4*)(x + row1);
        const float4* k1 = (const float4*)(k + row1);
        #pragma unroll
        for (int it = 0; it < L_ / 4 / THREADS; it++) {
            const int v = it * THREADS + tid;       // float4 index
            float4 xa = x0[v], ka = k0[v];
            float4 xb = x1[v], kb = k1[v];
            float a0[4] = {ka.x * xa.x, ka.y * xa.y, ka.z * xa.z, ka.w * xa.w};
            float a1[4] = {kb.x * xb.x, kb.y * xb.y, kb.z * xb.z, kb.w * xb.w};
            #pragma unroll
            for (int j = 0; j < 4; j++)
                sh[padidx(HL_ - 1 + v * 4 + j)] =
                    ((u64)__float_as_uint(a1[j]) << 32) | (u64)__float_as_uint(a0[j]);
        }
    }
    __syncthreads();

    const int l0 = tid * TPT;

    u64 acc[TPT];
    #pragma unroll
    for (int t = 0; t < TPT; t++) acc[t] = 0ULL;

    #pragma unroll 1
    for (int c = 0; c < HL_ / U; c++) {
        const int wbase = HL_ - 1 + l0 - U * c - (U - 1);
        u64 win[TPT + U - 1];
        #pragma unroll
        for (int j = 0; j < TPT + U - 1; j++) win[j] = sh[padidx(wbase + j)];
        #pragma unroll
        for (int u = 0; u < U; u++) {
            const u64 wv = w2[U * c + u];   // uniform across warp -> broadcast
            #pragma unroll
            for (int t = 0; t < TPT; t++)
                ffma2(acc[t], win[(U - 1 - u) + t], wv);
        }
    }

    // Epilogue: gate by q, float4 stores for both channels.
    {
        const float4* q0 = (const float4*)(q + row0 + l0);
        const float4* q1 = (const float4*)(q + row1 + l0);
        float4* o0 = (float4*)(out + row0 + l0);
        float4* o1 = (float4*)(out + row1 + l0);
        #pragma unroll
        for (int t4 = 0; t4 < TPT / 4; t4++) {
            float4 qa = q0[t4], qb = q1[t4];
            float4 ra, rb;
            float* pa = &ra.x; float* pb = &rb.x;
            const float* pqa = &qa.x; const float* pqb = &qb.x;
            #pragma unroll
            for (int j = 0; j < 4; j++) {
                u64 a = acc[t4 * 4 + j];
                pa[j] = pqa[j] * __uint_as_float((unsigned)(a & 0xffffffffULL));
                pb[j] = pqb[j] * __uint_as_float((unsigned)(a >> 32));
            }
            o0[t4] = ra;
            o1[t4] = rb;
        }
    }
}

extern "C" void kernel_launch(void* const* d_in, const int* in_sizes, int n_in,
                              void* d_out, int out_size) {
    // metadata order: x, k, q, h  (all float32); output float32 (B,D,L)
    const float* x = (const float*)d_in[0];
    const float* k = (const float*)d_in[1];
    const float* q = (const float*)d_in[2];
    const float* h = (const float*)d_in[3];
    float* out = (float*)d_out;

    dim3 grid(B_ * (D_ / 2));   // 4096 blocks: (batch, channel-pair)
    hyena_se_kernel<<<grid, THREADS>>>(x, k, q, h, out);
}